// round 15
// baseline (speedup 1.0000x reference)
#include <cuda_runtime.h>
#include <cuda_bf16.h>
#include <cstdint>

#define THREADS 256
#define TILE    64
#define KC      128
#define NPIX    (16 * 8192)
#define KPB     272              // B-image row stride bytes ([px][k], 128 k + pad)
#define CKB     144              // A-chunk row stride bytes (64 k + pad)
#define PITCH   66               // f32 pitched row stride (elems)

// dynamic smem byte offsets
#define WS_OFF  0                // 55296: W chunk (3 parts x 128 o x 144B); aliased by logits at end
#define XB_OFF  55296            // 52224: x / x2 image, parts at +0 / +17408 / +34816
#define HB_OFF  107520           // 52224: h image, 3 parts
#define HF_OFF  159744           // 33792: h fp32 [128][PITCH]
#define RF_OFF  193536           // 33792: r fp32 [128][PITCH]
#define SMEM_BYTES 227328

typedef unsigned long long ull;

// chunked 3-part weight images: [s][kc*27648 + part*9216 + o*72 + kk] (bf16 elems)
__device__ __nv_bfloat16 g_Wimg[4][55296];
__device__ float g_bias[4][KC];

__device__ __forceinline__ float lrelu_f(float x) { return x >= 0.0f ? x : 0.01f * x; }

__device__ __forceinline__ uint32_t smem_u32(const void* p) {
    uint32_t a; asm("{ .reg .u64 t; cvta.to.shared.u64 t, %1; cvt.u32.u64 %0, t; }" : "=r"(a) : "l"(p));
    return a;
}
__device__ __forceinline__ void ldsm4(uint32_t a, uint32_t* r) {
    asm volatile("ldmatrix.sync.aligned.m8n8.x4.shared.b16 {%0,%1,%2,%3}, [%4];"
                 : "=r"(r[0]), "=r"(r[1]), "=r"(r[2]), "=r"(r[3]) : "r"(a));
}
__device__ __forceinline__ void mma_bf16(float* c, const uint32_t* a, uint32_t b0, uint32_t b1) {
    asm volatile("mma.sync.aligned.m16n8k16.row.col.f32.bf16.bf16.f32 "
                 "{%0,%1,%2,%3}, {%4,%5,%6,%7}, {%8,%9}, {%0,%1,%2,%3};"
                 : "+f"(c[0]), "+f"(c[1]), "+f"(c[2]), "+f"(c[3])
                 : "r"(a[0]), "r"(a[1]), "r"(a[2]), "r"(a[3]), "r"(b0), "r"(b1));
}
// 3-way bf16 split store into a B image ([px][k], parts +0/+17408/+34816)
__device__ __forceinline__ void store_split3(char* b, int px, int o, float v) {
    __nv_bfloat16 h1 = __float2bfloat16(v);
    float r1 = v - __bfloat162float(h1);
    __nv_bfloat16 h2 = __float2bfloat16(r1);
    __nv_bfloat16 h3 = __float2bfloat16(r1 - __bfloat162float(h2));
    *(__nv_bfloat16*)(b + px * KPB + o * 2)         = h1;
    *(__nv_bfloat16*)(b + 17408 + px * KPB + o * 2) = h2;
    *(__nv_bfloat16*)(b + 34816 + px * KPB + o * 2) = h3;
}

__device__ __forceinline__ ull packdup(float x) { ull r; asm("mov.b64 %0, {%1,%1};" : "=l"(r) : "f"(x)); return r; }
__device__ __forceinline__ ull ffma2(ull a, ull b, ull c) { ull d; asm("fma.rn.f32x2 %0, %1, %2, %3;" : "=l"(d) : "l"(a), "l"(b), "l"(c)); return d; }
__device__ __forceinline__ float2 unpack2(ull v) { float2 f; asm("mov.b64 {%0,%1}, %2;" : "=f"(f.x), "=f"(f.y) : "l"(v)); return f; }

// ---------------- prep: BN-fold, bf16 3-way split, chunked [kc][part][o][kk] layout -------
__global__ void prep_kernel(const float* __restrict__ cl1_w, const float* __restrict__ cl1_b,
                            const float* __restrict__ cl1_g, const float* __restrict__ cl1_bt,
                            const float* __restrict__ cl1_m, const float* __restrict__ cl1_v,
                            const float* __restrict__ cl2_w, const float* __restrict__ cl2_b,
                            const float* __restrict__ cl3_w, const float* __restrict__ cl3_b,
                            const float* __restrict__ reg1_w, const float* __restrict__ reg1_b,
                            const float* __restrict__ reg1_g, const float* __restrict__ reg1_bt,
                            const float* __restrict__ reg1_m, const float* __restrict__ reg1_v)
{
    int t = blockIdx.x * blockDim.x + threadIdx.x;
    if (t < 4 * KC * KC) {
        int s = t >> 14, idx = t & 16383, o = idx >> 7, k = idx & 127;
        const float* W = (s == 0) ? cl1_w : (s == 1) ? reg1_w : (s == 2) ? cl2_w : cl3_w;
        float sc = 1.0f;
        if (s == 0)      sc = cl1_g[o]  * rsqrtf(cl1_v[o]  + 1e-5f);
        else if (s == 1) sc = reg1_g[o] * rsqrtf(reg1_v[o] + 1e-5f);
        float v = W[o * KC + k] * sc;
        __nv_bfloat16 h1 = __float2bfloat16(v);
        float r1 = v - __bfloat162float(h1);
        __nv_bfloat16 h2 = __float2bfloat16(r1);
        __nv_bfloat16 h3 = __float2bfloat16(r1 - __bfloat162float(h2));
        int kc = k >> 6, kk = k & 63;
        int base = kc * 27648 + o * 72 + kk;
        g_Wimg[s][base]         = h1;
        g_Wimg[s][base + 9216]  = h2;
        g_Wimg[s][base + 18432] = h3;
    }
    if (t < 4 * KC) {
        int s = t >> 7, o = t & 127;
        float b;
        if (s == 0)      b = (cl1_b[o]  - cl1_m[o])  * (cl1_g[o]  * rsqrtf(cl1_v[o]  + 1e-5f)) + cl1_bt[o];
        else if (s == 1) b = (reg1_b[o] - reg1_m[o]) * (reg1_g[o] * rsqrtf(reg1_v[o] + 1e-5f)) + reg1_bt[o];
        else if (s == 2) b = cl2_b[o];
        else             b = cl3_b[o];
        g_bias[s][o] = b;
    }
}

// ---------------- fused main kernel (mma.sync bf16x3, 6-term, ~fp32 precision) ------------
__global__ __launch_bounds__(THREADS, 1)
void fused_mma_kernel(const float* __restrict__ x_in,
                      const float* __restrict__ cl3_w, const float* __restrict__ cl3_b,
                      const float* __restrict__ w2,    const float* __restrict__ b2,
                      const float* __restrict__ w3,    const float* __restrict__ b3,
                      float* __restrict__ out)
{
    extern __shared__ __align__(16) char smc[];
    const uint32_t smb = smem_u32(smc);

    __shared__ float sbias[4][KC];
    __shared__ int   s_ind[TILE];
    __shared__ float s_pred[TILE][4];

    const int tid  = threadIdx.x;
    const int wid  = tid >> 5;
    const int lane = tid & 31;
    const int g    = lane >> 2;
    const int tig  = lane & 3;
    const int gp0  = blockIdx.x * TILE;
    const int bb   = gp0 >> 13;
    const int w0   = gp0 & 8191;

    if (tid < KC) {
#pragma unroll
        for (int s = 0; s < 4; s++) sbias[s][tid] = g_bias[s][tid];
    }

    // ---- load x, 3-way split into XB [px][k] --------------------------------------------
    {
        char* xb = smc + XB_OFF;
        for (int i = tid; i < KC * TILE; i += THREADS) {
            int c = i >> 6, px = i & 63;
            float v = x_in[((size_t)bb * KC + c) * 8192 + w0 + px];
            store_split3(xb, px, c, v);
        }
    }

    // ldmatrix lane offsets (same fragment plumbing as validated R13, strides updated)
    const int mId = lane >> 3;
    const uint32_t aLaneC = (uint32_t)((wid * 16 + (mId & 1) * 8 + (lane & 7)) * CKB + (mId >> 1) * 16);
    uint32_t bLane[4];
#pragma unroll
    for (int nt = 0; nt < 4; nt++)
        bLane[nt] = (uint32_t)((nt * 16 + (mId >> 1) * 8 + (lane & 7)) * KPB + (mId & 1) * 16);

    float acc[8][4];

#pragma unroll 1
    for (int s = 0; s < 4; s++) {
        const uint32_t bBase = smb + ((s == 2) ? HB_OFF : XB_OFF);
#pragma unroll
        for (int j = 0; j < 8; j++)
#pragma unroll
            for (int e = 0; e < 4; e++) acc[j][e] = 0.0f;

#pragma unroll 1
        for (int kc = 0; kc < 2; kc++) {
            __syncthreads();                           // prior consumers of WS done
            {   // stage W chunk: 55296 B = 3456 uint4
                const uint4* src = (const uint4*)(&g_Wimg[s][kc * 27648]);
                uint4* dst = (uint4*)(smc + WS_OFF);
                for (int i = tid; i < 3456; i += THREADS) dst[i] = src[i];
            }
            __syncthreads();
#pragma unroll
            for (int ks = 0; ks < 4; ks++) {
                uint32_t a1[4], a2[4], a3[4];
                uint32_t ka = smb + WS_OFF + aLaneC + ks * 32;
                ldsm4(ka,         a1);
                ldsm4(ka + 18432, a2);
                ldsm4(ka + 36864, a3);
                int ksg = kc * 4 + ks;
#pragma unroll
                for (int nt = 0; nt < 4; nt++) {
                    uint32_t b1[4], b2[4], b3[4];
                    uint32_t kb = bBase + bLane[nt] + ksg * 32;
                    ldsm4(kb,         b1);
                    ldsm4(kb + 17408, b2);
                    ldsm4(kb + 34816, b3);
                    float* cl = acc[nt * 2];
                    float* ch = acc[nt * 2 + 1];
                    mma_bf16(cl, a1, b1[0], b1[1]);
                    mma_bf16(cl, a1, b2[0], b2[1]);
                    mma_bf16(cl, a2, b1[0], b1[1]);
                    mma_bf16(cl, a2, b2[0], b2[1]);
                    mma_bf16(cl, a1, b3[0], b3[1]);
                    mma_bf16(cl, a3, b1[0], b1[1]);
                    mma_bf16(ch, a1, b1[2], b1[3]);
                    mma_bf16(ch, a1, b2[2], b2[3]);
                    mma_bf16(ch, a2, b1[2], b1[3]);
                    mma_bf16(ch, a2, b2[2], b2[3]);
                    mma_bf16(ch, a1, b3[2], b3[3]);
                    mma_bf16(ch, a3, b1[2], b1[3]);
                }
            }
        }

        if (s == 3) __syncthreads();   // all warps done reading WS -> safe to alias with logits

        const int oA = wid * 16 + g, oB = oA + 8;
        if (s == 0 || s == 2) {
            float bA = sbias[s][oA], bB = sbias[s][oB];
            char* img = smc + ((s == 0) ? HB_OFF : XB_OFF);
            float* Hf = (float*)(smc + HF_OFF);
#pragma unroll
            for (int j = 0; j < 8; j++) {
                int px = j * 8 + tig * 2;
                float v00 = lrelu_f(acc[j][0] + bA);
                float v01 = lrelu_f(acc[j][1] + bA);
                float v10 = lrelu_f(acc[j][2] + bB);
                float v11 = lrelu_f(acc[j][3] + bB);
                if (s == 0) {
                    Hf[oA * PITCH + px] = v00; Hf[oA * PITCH + px + 1] = v01;
                    Hf[oB * PITCH + px] = v10; Hf[oB * PITCH + px + 1] = v11;
                }
                store_split3(img, px,     oA, v00);
                store_split3(img, px + 1, oA, v01);
                store_split3(img, px,     oB, v10);
                store_split3(img, px + 1, oB, v11);
            }
        } else if (s == 1) {
            float bA = sbias[1][oA], bB = sbias[1][oB];
            float* Rf = (float*)(smc + RF_OFF);
#pragma unroll
            for (int j = 0; j < 8; j++) {
                int px = j * 8 + tig * 2;
                Rf[oA * PITCH + px]     = lrelu_f(acc[j][0] + bA);
                Rf[oA * PITCH + px + 1] = lrelu_f(acc[j][1] + bA);
                Rf[oB * PITCH + px]     = lrelu_f(acc[j][2] + bB);
                Rf[oB * PITCH + px + 1] = lrelu_f(acc[j][3] + bB);
            }
        } else {
            float bA = sbias[3][oA], bB = sbias[3][oB];
            float* LG = (float*)(smc + WS_OFF);
#pragma unroll
            for (int j = 0; j < 8; j++) {
                int px = j * 8 + tig * 2;
                LG[oA * PITCH + px]     = acc[j][0] + bA;
                LG[oA * PITCH + px + 1] = acc[j][1] + bA;
                LG[oB * PITCH + px]     = acc[j][2] + bB;
                LG[oB * PITCH + px + 1] = acc[j][3] + bB;
            }
        }
    }
    __syncthreads();

    // ---- argmax (first-max, ascending o) + mask channel ---------------------------------
    if (tid < TILE) {
        int p = tid;
        const float* LG = (const float*)(smc + WS_OFF);
        float mv = LG[p]; int mi = 0;
#pragma unroll 4
        for (int o = 1; o < 128; o++) {
            float v = LG[o * PITCH + p];
            if (v > mv) { mv = v; mi = o; }
        }
        s_ind[p] = mi;
        // mask: cl3 row 128 . x2  (x2 = 3-part sum from XB)
        const char* x1 = smc + XB_OFF;
        const char* x2 = x1 + 17408;
        const char* x3 = x1 + 34816;
        const float* mrow = cl3_w + 128 * KC;
        float macc = __ldg(cl3_b + 128);
#pragma unroll 4
        for (int k4 = 0; k4 < 32; k4++) {
            ull v1 = *(const ull*)(x1 + p * KPB + k4 * 8);
            ull v2 = *(const ull*)(x2 + p * KPB + k4 * 8);
            ull v3 = *(const ull*)(x3 + p * KPB + k4 * 8);
#pragma unroll
            for (int e = 0; e < 4; e++) {
                uint16_t u1 = (uint16_t)(v1 >> (16 * e));
                uint16_t u2 = (uint16_t)(v2 >> (16 * e));
                uint16_t u3 = (uint16_t)(v3 >> (16 * e));
                float xv = __bfloat162float(*(__nv_bfloat16*)&u1)
                         + __bfloat162float(*(__nv_bfloat16*)&u2)
                         + __bfloat162float(*(__nv_bfloat16*)&u3);
                macc = fmaf(__ldg(mrow + k4 * 4 + e), xv, macc);
            }
        }
        out[NPIX + gp0 + p] = lrelu_f(macc);
    }
    __syncthreads();

    // ---- stage 5: y = lrelu(cat[r;h] @ w2[sp] + b2[sp]); reg = y . w3[ind] --------------
    {
        int q = tid >> 6;                 // 0..3 -> outputs q*8..q*8+8
        int p = tid & 63;
        int ind = s_ind[p];
        int sp  = ind >> 4;
        const float* Rf = (const float*)(smc + RF_OFF);
        const float* Hf = (const float*)(smc + HF_OFF);
        const float* wp = w2 + (size_t)sp * (256 * 32) + q * 8;
        const ulonglong2* binit = (const ulonglong2*)(b2 + sp * 32 + q * 8);
        ulonglong2 t0 = binit[0], t1 = binit[1];
        ull y[4] = { t0.x, t0.y, t1.x, t1.y };
#pragma unroll 4
        for (int f = 0; f < 128; f++) {
            ull c = packdup(Rf[f * PITCH + p]);
            const ulonglong2* wq = (const ulonglong2*)(wp + f * 32);
            ulonglong2 u0 = wq[0], u1 = wq[1];
            y[0] = ffma2(c, u0.x, y[0]); y[1] = ffma2(c, u0.y, y[1]);
            y[2] = ffma2(c, u1.x, y[2]); y[3] = ffma2(c, u1.y, y[3]);
        }
#pragma unroll 4
        for (int f = 0; f < 128; f++) {
            ull c = packdup(Hf[f * PITCH + p]);
            const ulonglong2* wq = (const ulonglong2*)(wp + (128 + f) * 32);
            ulonglong2 u0 = wq[0], u1 = wq[1];
            y[0] = ffma2(c, u0.x, y[0]); y[1] = ffma2(c, u0.y, y[1]);
            y[2] = ffma2(c, u1.x, y[2]); y[3] = ffma2(c, u1.y, y[3]);
        }
        const float* w3p = w3 + ind * 32 + q * 8;
        float part = 0.0f;
#pragma unroll
        for (int r = 0; r < 4; r++) {
            float2 v = unpack2(y[r]);
            part = fmaf(lrelu_f(v.x), __ldg(w3p + 2 * r),     part);
            part = fmaf(lrelu_f(v.y), __ldg(w3p + 2 * r + 1), part);
        }
        s_pred[p][q] = part;
    }
    __syncthreads();
    if (tid < TILE) {
        int p = tid;
        int ind = s_ind[p];
        float reg = s_pred[p][0] + s_pred[p][1] + s_pred[p][2] + s_pred[p][3] + __ldg(b3 + ind);
        out[gp0 + p] = ((float)ind + reg) * 0.0078125f;
    }
}

extern "C" void kernel_launch(void* const* d_in, const int* in_sizes, int n_in,
                              void* d_out, int out_size) {
    if (n_in < 21 || d_out == nullptr) return;

    const float* x_in    = (const float*)d_in[0];
    const float* cl1_w   = (const float*)d_in[1];
    const float* cl1_b   = (const float*)d_in[2];
    const float* cl1_g   = (const float*)d_in[3];
    const float* cl1_bt  = (const float*)d_in[4];
    const float* cl1_m   = (const float*)d_in[5];
    const float* cl1_v   = (const float*)d_in[6];
    const float* cl2_w   = (const float*)d_in[7];
    const float* cl2_b   = (const float*)d_in[8];
    const float* cl3_w   = (const float*)d_in[9];
    const float* cl3_b   = (const float*)d_in[10];
    const float* reg1_w  = (const float*)d_in[11];
    const float* reg1_b  = (const float*)d_in[12];
    const float* reg1_g  = (const float*)d_in[13];
    const float* reg1_bt = (const float*)d_in[14];
    const float* reg1_m  = (const float*)d_in[15];
    const float* reg1_v  = (const float*)d_in[16];
    const float* w2      = (const float*)d_in[17];
    const float* b2      = (const float*)d_in[18];
    const float* w3      = (const float*)d_in[19];
    const float* b3      = (const float*)d_in[20];
    float* out = (float*)d_out;

    prep_kernel<<<(4 * 128 * 128 + 255) / 256, 256>>>(
        cl1_w, cl1_b, cl1_g, cl1_bt, cl1_m, cl1_v,
        cl2_w, cl2_b, cl3_w, cl3_b,
        reg1_w, reg1_b, reg1_g, reg1_bt, reg1_m, reg1_v);

    cudaFuncSetAttribute(fused_mma_kernel,
                         cudaFuncAttributeMaxDynamicSharedMemorySize, SMEM_BYTES);
    fused_mma_kernel<<<NPIX / TILE, THREADS, SMEM_BYTES>>>(
        x_in, cl3_w, cl3_b, w2, b2, w3, b3, out);
}

// round 16
// speedup vs baseline: 1.0280x; 1.0280x over previous
#include <cuda_runtime.h>
#include <cuda_bf16.h>
#include <cstdint>

#define THREADS 512
#define TILE    64
#define KC      128
#define NPIX    (16 * 8192)
#define KPB     272              // B-image row stride bytes ([px][k], 128 k + pad)
#define CKB     144              // A-chunk row stride bytes (64 k + pad)
#define PITCH   66               // f32 pitched row stride (elems)

// dynamic smem byte offsets
#define WS_OFF  0                // 55296: W chunk (3 parts x 128 o x 144B); aliased by logits at end
#define XB_OFF  55296            // 52224: x / x2 image, parts at +0 / +17408 / +34816
#define HB_OFF  107520           // 52224: h image, 3 parts
#define HF_OFF  159744           // 33792: h fp32 [128][PITCH]
#define RF_OFF  193536           // 33792: r fp32 [128][PITCH]
#define SMEM_BYTES 227328

typedef unsigned long long ull;

// chunked 3-part weight images: [s][kc*27648 + part*9216 + o*72 + kk] (bf16 elems)
__device__ __nv_bfloat16 g_Wimg[4][55296];
__device__ float g_bias[4][KC];

__device__ __forceinline__ float lrelu_f(float x) { return x >= 0.0f ? x : 0.01f * x; }

__device__ __forceinline__ uint32_t smem_u32(const void* p) {
    uint32_t a; asm("{ .reg .u64 t; cvta.to.shared.u64 t, %1; cvt.u32.u64 %0, t; }" : "=r"(a) : "l"(p));
    return a;
}
__device__ __forceinline__ void ldsm4(uint32_t a, uint32_t* r) {
    asm volatile("ldmatrix.sync.aligned.m8n8.x4.shared.b16 {%0,%1,%2,%3}, [%4];"
                 : "=r"(r[0]), "=r"(r[1]), "=r"(r[2]), "=r"(r[3]) : "r"(a));
}
__device__ __forceinline__ void mma_bf16(float* c, const uint32_t* a, uint32_t b0, uint32_t b1) {
    asm volatile("mma.sync.aligned.m16n8k16.row.col.f32.bf16.bf16.f32 "
                 "{%0,%1,%2,%3}, {%4,%5,%6,%7}, {%8,%9}, {%0,%1,%2,%3};"
                 : "+f"(c[0]), "+f"(c[1]), "+f"(c[2]), "+f"(c[3])
                 : "r"(a[0]), "r"(a[1]), "r"(a[2]), "r"(a[3]), "r"(b0), "r"(b1));
}
#define CP_ASYNC16(dst, src) \
    asm volatile("cp.async.cg.shared.global [%0], [%1], 16;" :: "r"(dst), "l"(src) : "memory")
#define CP_WAIT_ALL() \
    asm volatile("cp.async.commit_group;\n\tcp.async.wait_group 0;" ::: "memory")

// 3-way bf16 split store into a B image ([px][k], parts +0/+17408/+34816)
__device__ __forceinline__ void store_split3(char* b, int px, int o, float v) {
    __nv_bfloat16 h1 = __float2bfloat16(v);
    float r1 = v - __bfloat162float(h1);
    __nv_bfloat16 h2 = __float2bfloat16(r1);
    __nv_bfloat16 h3 = __float2bfloat16(r1 - __bfloat162float(h2));
    *(__nv_bfloat16*)(b + px * KPB + o * 2)         = h1;
    *(__nv_bfloat16*)(b + 17408 + px * KPB + o * 2) = h2;
    *(__nv_bfloat16*)(b + 34816 + px * KPB + o * 2) = h3;
}

__device__ __forceinline__ ull packdup(float x) { ull r; asm("mov.b64 %0, {%1,%1};" : "=l"(r) : "f"(x)); return r; }
__device__ __forceinline__ ull ffma2(ull a, ull b, ull c) { ull d; asm("fma.rn.f32x2 %0, %1, %2, %3;" : "=l"(d) : "l"(a), "l"(b), "l"(c)); return d; }
__device__ __forceinline__ float2 unpack2(ull v) { float2 f; asm("mov.b64 {%0,%1}, %2;" : "=f"(f.x), "=f"(f.y) : "l"(v)); return f; }

// ---------------- prep: BN-fold, bf16 3-way split, chunked [kc][part][o][kk] layout -------
__global__ void prep_kernel(const float* __restrict__ cl1_w, const float* __restrict__ cl1_b,
                            const float* __restrict__ cl1_g, const float* __restrict__ cl1_bt,
                            const float* __restrict__ cl1_m, const float* __restrict__ cl1_v,
                            const float* __restrict__ cl2_w, const float* __restrict__ cl2_b,
                            const float* __restrict__ cl3_w, const float* __restrict__ cl3_b,
                            const float* __restrict__ reg1_w, const float* __restrict__ reg1_b,
                            const float* __restrict__ reg1_g, const float* __restrict__ reg1_bt,
                            const float* __restrict__ reg1_m, const float* __restrict__ reg1_v)
{
    int t = blockIdx.x * blockDim.x + threadIdx.x;
    if (t < 4 * KC * KC) {
        int s = t >> 14, idx = t & 16383, o = idx >> 7, k = idx & 127;
        const float* W = (s == 0) ? cl1_w : (s == 1) ? reg1_w : (s == 2) ? cl2_w : cl3_w;
        float sc = 1.0f;
        if (s == 0)      sc = cl1_g[o]  * rsqrtf(cl1_v[o]  + 1e-5f);
        else if (s == 1) sc = reg1_g[o] * rsqrtf(reg1_v[o] + 1e-5f);
        float v = W[o * KC + k] * sc;
        __nv_bfloat16 h1 = __float2bfloat16(v);
        float r1 = v - __bfloat162float(h1);
        __nv_bfloat16 h2 = __float2bfloat16(r1);
        __nv_bfloat16 h3 = __float2bfloat16(r1 - __bfloat162float(h2));
        int kc = k >> 6, kk = k & 63;
        int base = kc * 27648 + o * 72 + kk;
        g_Wimg[s][base]         = h1;
        g_Wimg[s][base + 9216]  = h2;
        g_Wimg[s][base + 18432] = h3;
    }
    if (t < 4 * KC) {
        int s = t >> 7, o = t & 127;
        float b;
        if (s == 0)      b = (cl1_b[o]  - cl1_m[o])  * (cl1_g[o]  * rsqrtf(cl1_v[o]  + 1e-5f)) + cl1_bt[o];
        else if (s == 1) b = (reg1_b[o] - reg1_m[o]) * (reg1_g[o] * rsqrtf(reg1_v[o] + 1e-5f)) + reg1_bt[o];
        else if (s == 2) b = cl2_b[o];
        else             b = cl3_b[o];
        g_bias[s][o] = b;
    }
}

// ---------------- fused main kernel (mma.sync bf16x3, 6-term, 16 warps) -------------------
__global__ __launch_bounds__(THREADS, 1)
void fused_mma_kernel(const float* __restrict__ x_in,
                      const float* __restrict__ cl3_w, const float* __restrict__ cl3_b,
                      const float* __restrict__ w2,    const float* __restrict__ b2,
                      const float* __restrict__ w3,    const float* __restrict__ b3,
                      float* __restrict__ out)
{
    extern __shared__ __align__(16) char smc[];
    const uint32_t smb = smem_u32(smc);

    __shared__ float sbias[4][KC];
    __shared__ int   s_ind[TILE];
    __shared__ float s_pred[TILE][8];

    const int tid  = threadIdx.x;
    const int wid  = tid >> 5;        // 0..15
    const int lane = tid & 31;
    const int og   = wid >> 1;        // 0..7 : o-group of 16
    const int ph   = wid & 1;         // 0/1  : px-half of 32
    const int g    = lane >> 2;
    const int tig  = lane & 3;
    const int gp0  = blockIdx.x * TILE;
    const int bb   = gp0 >> 13;
    const int w0   = gp0 & 8191;

    if (tid < KC) {
#pragma unroll
        for (int s = 0; s < 4; s++) sbias[s][tid] = g_bias[s][tid];
    }

    // ---- load x, 3-way split into XB [px][k] --------------------------------------------
    {
        char* xb = smc + XB_OFF;
        for (int i = tid; i < KC * TILE; i += THREADS) {
            int c = i >> 6, px = i & 63;
            float v = x_in[((size_t)bb * KC + c) * 8192 + w0 + px];
            store_split3(xb, px, c, v);
        }
    }

    // ldmatrix lane offsets (fragment plumbing validated in R15; tiles re-based)
    const int mId = lane >> 3;
    const uint32_t aLaneC = (uint32_t)((og * 16 + (mId & 1) * 8 + (lane & 7)) * CKB + (mId >> 1) * 16);
    uint32_t bLane[2];
#pragma unroll
    for (int nt = 0; nt < 2; nt++)
        bLane[nt] = (uint32_t)((ph * 32 + nt * 16 + (mId >> 1) * 8 + (lane & 7)) * KPB + (mId & 1) * 16);

    float acc[4][4];

#pragma unroll 1
    for (int s = 0; s < 4; s++) {
        const uint32_t bBase = smb + ((s == 2) ? HB_OFF : XB_OFF);
#pragma unroll
        for (int j = 0; j < 4; j++)
#pragma unroll
            for (int e = 0; e < 4; e++) acc[j][e] = 0.0f;

#pragma unroll 1
        for (int kc = 0; kc < 2; kc++) {
            __syncthreads();                           // prior consumers of WS done
            {   // stage W chunk via cp.async: 55296 B = 3456 x 16B
                const char* src = (const char*)(&g_Wimg[s][kc * 27648]);
                for (int i = tid; i < 3456; i += THREADS)
                    CP_ASYNC16(smb + WS_OFF + i * 16, src + i * 16);
                CP_WAIT_ALL();
            }
            __syncthreads();
#pragma unroll
            for (int ks = 0; ks < 4; ks++) {
                uint32_t a1[4], a2[4], a3[4];
                uint32_t ka = smb + WS_OFF + aLaneC + ks * 32;
                ldsm4(ka,         a1);
                ldsm4(ka + 18432, a2);
                ldsm4(ka + 36864, a3);
                int ksg = kc * 4 + ks;
#pragma unroll
                for (int nt = 0; nt < 2; nt++) {
                    uint32_t b1[4], b2[4], b3[4];
                    uint32_t kb = bBase + bLane[nt] + ksg * 32;
                    ldsm4(kb,         b1);
                    ldsm4(kb + 17408, b2);
                    ldsm4(kb + 34816, b3);
                    float* cl = acc[nt * 2];
                    float* ch = acc[nt * 2 + 1];
                    mma_bf16(cl, a1, b1[0], b1[1]);
                    mma_bf16(cl, a1, b2[0], b2[1]);
                    mma_bf16(cl, a2, b1[0], b1[1]);
                    mma_bf16(cl, a2, b2[0], b2[1]);
                    mma_bf16(cl, a1, b3[0], b3[1]);
                    mma_bf16(cl, a3, b1[0], b1[1]);
                    mma_bf16(ch, a1, b1[2], b1[3]);
                    mma_bf16(ch, a1, b2[2], b2[3]);
                    mma_bf16(ch, a2, b1[2], b1[3]);
                    mma_bf16(ch, a2, b2[2], b2[3]);
                    mma_bf16(ch, a1, b3[2], b3[3]);
                    mma_bf16(ch, a3, b1[2], b1[3]);
                }
            }
        }

        if (s == 3) __syncthreads();   // all warps done reading WS -> safe to alias with logits

        const int oA = og * 16 + g, oB = oA + 8;
        if (s == 0 || s == 2) {
            float bA = sbias[s][oA], bB = sbias[s][oB];
            char* img = smc + ((s == 0) ? HB_OFF : XB_OFF);
            float* Hf = (float*)(smc + HF_OFF);
#pragma unroll
            for (int j = 0; j < 4; j++) {
                int px = ph * 32 + j * 8 + tig * 2;
                float v00 = lrelu_f(acc[j][0] + bA);
                float v01 = lrelu_f(acc[j][1] + bA);
                float v10 = lrelu_f(acc[j][2] + bB);
                float v11 = lrelu_f(acc[j][3] + bB);
                if (s == 0) {
                    Hf[oA * PITCH + px] = v00; Hf[oA * PITCH + px + 1] = v01;
                    Hf[oB * PITCH + px] = v10; Hf[oB * PITCH + px + 1] = v11;
                }
                store_split3(img, px,     oA, v00);
                store_split3(img, px + 1, oA, v01);
                store_split3(img, px,     oB, v10);
                store_split3(img, px + 1, oB, v11);
            }
        } else if (s == 1) {
            float bA = sbias[1][oA], bB = sbias[1][oB];
            float* Rf = (float*)(smc + RF_OFF);
#pragma unroll
            for (int j = 0; j < 4; j++) {
                int px = ph * 32 + j * 8 + tig * 2;
                Rf[oA * PITCH + px]     = lrelu_f(acc[j][0] + bA);
                Rf[oA * PITCH + px + 1] = lrelu_f(acc[j][1] + bA);
                Rf[oB * PITCH + px]     = lrelu_f(acc[j][2] + bB);
                Rf[oB * PITCH + px + 1] = lrelu_f(acc[j][3] + bB);
            }
        } else {
            float bA = sbias[3][oA], bB = sbias[3][oB];
            float* LG = (float*)(smc + WS_OFF);
#pragma unroll
            for (int j = 0; j < 4; j++) {
                int px = ph * 32 + j * 8 + tig * 2;
                LG[oA * PITCH + px]     = acc[j][0] + bA;
                LG[oA * PITCH + px + 1] = acc[j][1] + bA;
                LG[oB * PITCH + px]     = acc[j][2] + bB;
                LG[oB * PITCH + px + 1] = acc[j][3] + bB;
            }
        }
    }
    __syncthreads();

    // ---- argmax (first-max, ascending o) + mask channel ---------------------------------
    if (tid < TILE) {
        int p = tid;
        const float* LG = (const float*)(smc + WS_OFF);
        float mv = LG[p]; int mi = 0;
#pragma unroll 4
        for (int o = 1; o < 128; o++) {
            float v = LG[o * PITCH + p];
            if (v > mv) { mv = v; mi = o; }
        }
        s_ind[p] = mi;
        // mask: cl3 row 128 . x2  (x2 = 3-part sum from XB)
        const char* x1 = smc + XB_OFF;
        const char* x2 = x1 + 17408;
        const char* x3 = x1 + 34816;
        const float* mrow = cl3_w + 128 * KC;
        float macc = __ldg(cl3_b + 128);
#pragma unroll 4
        for (int k4 = 0; k4 < 32; k4++) {
            ull v1 = *(const ull*)(x1 + p * KPB + k4 * 8);
            ull v2 = *(const ull*)(x2 + p * KPB + k4 * 8);
            ull v3 = *(const ull*)(x3 + p * KPB + k4 * 8);
#pragma unroll
            for (int e = 0; e < 4; e++) {
                uint16_t u1 = (uint16_t)(v1 >> (16 * e));
                uint16_t u2 = (uint16_t)(v2 >> (16 * e));
                uint16_t u3 = (uint16_t)(v3 >> (16 * e));
                float xv = __bfloat162float(*(__nv_bfloat16*)&u1)
                         + __bfloat162float(*(__nv_bfloat16*)&u2)
                         + __bfloat162float(*(__nv_bfloat16*)&u3);
                macc = fmaf(__ldg(mrow + k4 * 4 + e), xv, macc);
            }
        }
        out[NPIX + gp0 + p] = lrelu_f(macc);
    }
    __syncthreads();

    // ---- stage 5: y = lrelu(cat[r;h] @ w2[sp] + b2[sp]); reg = y . w3[ind] --------------
    {
        int q = tid >> 6;                 // 0..7 -> outputs q*4..q*4+4
        int p = tid & 63;
        int ind = s_ind[p];
        int sp  = ind >> 4;
        const float* Rf = (const float*)(smc + RF_OFF);
        const float* Hf = (const float*)(smc + HF_OFF);
        const float* wp = w2 + (size_t)sp * (256 * 32) + q * 4;
        const ulonglong2* binit = (const ulonglong2*)(b2 + sp * 32 + q * 4);
        ulonglong2 t0 = binit[0];
        ull y[2] = { t0.x, t0.y };
#pragma unroll 4
        for (int f = 0; f < 128; f++) {
            ull c = packdup(Rf[f * PITCH + p]);
            const ulonglong2* wq = (const ulonglong2*)(wp + f * 32);
            ulonglong2 u0 = wq[0];
            y[0] = ffma2(c, u0.x, y[0]); y[1] = ffma2(c, u0.y, y[1]);
        }
#pragma unroll 4
        for (int f = 0; f < 128; f++) {
            ull c = packdup(Hf[f * PITCH + p]);
            const ulonglong2* wq = (const ulonglong2*)(wp + (128 + f) * 32);
            ulonglong2 u0 = wq[0];
            y[0] = ffma2(c, u0.x, y[0]); y[1] = ffma2(c, u0.y, y[1]);
        }
        const float* w3p = w3 + ind * 32 + q * 4;
        float part = 0.0f;
#pragma unroll
        for (int r = 0; r < 2; r++) {
            float2 v = unpack2(y[r]);
            part = fmaf(lrelu_f(v.x), __ldg(w3p + 2 * r),     part);
            part = fmaf(lrelu_f(v.y), __ldg(w3p + 2 * r + 1), part);
        }
        s_pred[p][q] = part;
    }
    __syncthreads();
    if (tid < TILE) {
        int p = tid;
        int ind = s_ind[p];
        float reg = s_pred[p][0] + s_pred[p][1] + s_pred[p][2] + s_pred[p][3]
                  + s_pred[p][4] + s_pred[p][5] + s_pred[p][6] + s_pred[p][7]
                  + __ldg(b3 + ind);
        out[gp0 + p] = ((float)ind + reg) * 0.0078125f;
    }
}

extern "C" void kernel_launch(void* const* d_in, const int* in_sizes, int n_in,
                              void* d_out, int out_size) {
    if (n_in < 21 || d_out == nullptr) return;

    const float* x_in    = (const float*)d_in[0];
    const float* cl1_w   = (const float*)d_in[1];
    const float* cl1_b   = (const float*)d_in[2];
    const float* cl1_g   = (const float*)d_in[3];
    const float* cl1_bt  = (const float*)d_in[4];
    const float* cl1_m   = (const float*)d_in[5];
    const float* cl1_v   = (const float*)d_in[6];
    const float* cl2_w   = (const float*)d_in[7];
    const float* cl2_b   = (const float*)d_in[8];
    const float* cl3_w   = (const float*)d_in[9];
    const float* cl3_b   = (const float*)d_in[10];
    const float* reg1_w  = (const float*)d_in[11];
    const float* reg1_b  = (const float*)d_in[12];
    const float* reg1_g  = (const float*)d_in[13];
    const float* reg1_bt = (const float*)d_in[14];
    const float* reg1_m  = (const float*)d_in[15];
    const float* reg1_v  = (const float*)d_in[16];
    const float* w2      = (const float*)d_in[17];
    const float* b2      = (const float*)d_in[18];
    const float* w3      = (const float*)d_in[19];
    const float* b3      = (const float*)d_in[20];
    float* out = (float*)d_out;

    prep_kernel<<<(4 * 128 * 128 + 255) / 256, 256>>>(
        cl1_w, cl1_b, cl1_g, cl1_bt, cl1_m, cl1_v,
        cl2_w, cl2_b, cl3_w, cl3_b,
        reg1_w, reg1_b, reg1_g, reg1_bt, reg1_m, reg1_v);

    cudaFuncSetAttribute(fused_mma_kernel,
                         cudaFuncAttributeMaxDynamicSharedMemorySize, SMEM_BYTES);
    fused_mma_kernel<<<NPIX / TILE, THREADS, SMEM_BYTES>>>(
        x_in, cl3_w, cl3_b, w2, b2, w3, b3, out);
}